// round 11
// baseline (speedup 1.0000x reference)
#include <cuda_runtime.h>
#include <cuda_bf16.h>

// FlyVisAdExODE: event-driven COBA scatter + AdEx Euler step.
// N = 131072 neurons, E = N*64 = 8388608 edges.
//
// R7: single fused persistent kernel (148 blocks = #SMs, 1024 thr, 128KB
// smem => 1 block/SM, all co-resident) with software grid barriers.
//   Phase A: build byte activity codes (0 idle / 1 exc / 2 inh).
//   Phase B: stage 128KB code table in smem; scatter edges with packed
//            u32 counter atomics (exc low16 / inh hi16) — deterministic.
//   Phase C: AdEx Euler update; rezeroes g_cnt for the next launch
//            (g_cnt starts zeroed by static init; invariant re-established
//            every call => graph-replay safe and deterministic).
// Removes two kernel-launch latency floors (~4us each measured on prep).

#define NMAX   131072
#define NBLK   148
#define NTHR   1024

__device__ unsigned int  g_cnt[NMAX];     // zero-initialized at module load
__device__ unsigned char g_code[NMAX];
__device__ unsigned int  g_bar_cnt;       // barrier arrive counter
__device__ unsigned int  g_bar_gen;       // barrier generation (monotone)

__device__ __forceinline__ void grid_barrier() {
    __syncthreads();
    if (threadIdx.x == 0) {
        __threadfence();                              // order STG/RED before arrive
        unsigned my = *(volatile unsigned*)&g_bar_gen;
        if (atomicAdd(&g_bar_cnt, 1u) == (unsigned)(NBLK - 1)) {
            g_bar_cnt = 0u;
            __threadfence();
            *(volatile unsigned*)&g_bar_gen = my + 1u;
        } else {
            while (*(volatile unsigned*)&g_bar_gen == my) { }
        }
        __threadfence();
    }
    __syncthreads();
}

struct NeuronParams {
    const float *v, *w, *ge, *gi, *stim, *refr;
    const float *g_L, *delta_T, *v_thresh, *v_rest, *C, *a, *b;
    const float *tau_w, *tau_ge, *tau_gi;
    const float *E_ge, *E_gi, *I_bias, *stim_scale, *Q_ge, *Q_gi;
    const float *v_cut, *v_reset, *t_refrac;
    const float *dt_ptr;
    float* out;
    int n;
};

__device__ __forceinline__ void emit4(const int* __restrict__ dst, int t,
                                      unsigned c0, unsigned c1,
                                      unsigned c2, unsigned c3) {
    int4 d = __ldg(reinterpret_cast<const int4*>(dst) + t);
    if (c0) atomicAdd(&g_cnt[d.x], (c0 & 1u) | ((c0 & 2u) << 15));
    if (c1) atomicAdd(&g_cnt[d.y], (c1 & 1u) | ((c1 & 2u) << 15));
    if (c2) atomicAdd(&g_cnt[d.z], (c2 & 1u) | ((c2 & 2u) << 15));
    if (c3) atomicAdd(&g_cnt[d.w], (c3 & 1u) | ((c3 & 2u) << 15));
}

__device__ __forceinline__ uint4 ldcg4(const uint4* p) {
    return __ldcg(p);
}

__global__ __launch_bounds__(NTHR, 1)
void fused_kernel(const uint4* __restrict__ spiked,
                  const uint4* __restrict__ is_exc,
                  const int4* __restrict__ src4,
                  const int*  __restrict__ dst,
                  int e4, NeuronParams p) {
    extern __shared__ unsigned char tbl[];            // 131072 bytes
    const int g = blockIdx.x * NTHR + threadIdx.x;    // 0 .. 151551

    // ---- Phase A: build byte codes (first N/4 = 32768 threads) ----
    if (g < NMAX / 4) {
        uint4 s = spiked[g];
        uint4 e = is_exc[g];
        uchar4 c;
        c.x = s.x ? (e.x ? 1 : 2) : 0;
        c.y = s.y ? (e.y ? 1 : 2) : 0;
        c.z = s.z ? (e.z ? 1 : 2) : 0;
        c.w = s.w ? (e.w ? 1 : 2) : 0;
        reinterpret_cast<uchar4*>(g_code)[g] = c;
    }

    grid_barrier();

    // ---- Phase B: stage table, then scatter ----
    {
        const uint4* gc = reinterpret_cast<const uint4*>(g_code);
        uint4* st = reinterpret_cast<uint4*>(tbl);
        #pragma unroll
        for (int j = 0; j < 8; j++)
            st[threadIdx.x + j * NTHR] = ldcg4(gc + threadIdx.x + j * NTHR);
    }
    __syncthreads();

    const int T = NBLK * NTHR;
    int t = g;
    for (; t + T < e4; t += 2 * T) {
        int4 s0 = src4[t];
        int4 s1 = src4[t + T];
        unsigned a0 = tbl[s0.x], a1 = tbl[s0.y], a2 = tbl[s0.z], a3 = tbl[s0.w];
        unsigned b0 = tbl[s1.x], b1 = tbl[s1.y], b2 = tbl[s1.z], b3 = tbl[s1.w];
        if ((a0 | a1 | a2 | a3 | b0 | b1 | b2 | b3) != 0u) {
            if (a0 | a1 | a2 | a3) emit4(dst, t,     a0, a1, a2, a3);
            if (b0 | b1 | b2 | b3) emit4(dst, t + T, b0, b1, b2, b3);
        }
    }
    for (; t < e4; t += T) {
        int4 s = src4[t];
        unsigned c0 = tbl[s.x], c1 = tbl[s.y], c2 = tbl[s.z], c3 = tbl[s.w];
        if (c0 | c1 | c2 | c3) emit4(dst, t, c0, c1, c2, c3);
    }

    grid_barrier();

    // ---- Phase C: AdEx update (one neuron per thread) ----
    const int i = g;
    if (i >= p.n) return;

    const float dt = __ldg(p.dt_ptr);

    unsigned int cnt = __ldcg(&g_cnt[i]);
    g_cnt[i] = 0u;                        // re-arm for next launch
    float ge = p.ge[i] + p.Q_ge[i] * (float)(cnt & 0xFFFFu);
    float gi = p.gi[i] + p.Q_gi[i] * (float)(cnt >> 16);

    float v  = p.v[i];
    float w  = p.w[i];
    float gL = p.g_L[i];
    float dT = p.delta_T[i];
    float vr = p.v_rest[i];

    float I  = p.I_bias[i] + p.stim_scale[i] * p.stim[i]
             + ge * (p.E_ge[i] - v) + gi * (p.E_gi[i] - v);
    float ex = gL * dT * expf(fminf((v - p.v_thresh[i]) / dT, 20.0f));
    float dv = (-gL * (v - vr) + ex - w + I) / p.C[i];
    float dw = (-w + p.a[i] * (v - vr)) / p.tau_w[i];

    float refr = p.refr[i];
    float vn = (refr <= 0.0f) ? (v + dv * dt) : v;
    float wn = w + dw * dt;
    ge = ge - (ge / p.tau_ge[i]) * dt;
    gi = gi - (gi / p.tau_gi[i]) * dt;

    bool spk = vn > p.v_cut[i];
    vn = spk ? p.v_reset[i] : vn;
    wn = spk ? (wn + p.b[i]) : wn;
    float rf = (spk ? p.t_refrac[i] : refr) - dt;

    const int n = p.n;
    float* out = p.out;
    out[i]         = vn;
    out[n + i]     = wn;
    out[2 * n + i] = ge;
    out[3 * n + i] = gi;
    out[4 * n + i] = rf;
    out[5 * n + i] = spk ? 1.0f : 0.0f;
}

extern "C" void kernel_launch(void* const* d_in, const int* in_sizes, int n_in,
                              void* d_out, int out_size) {
    const int n = in_sizes[0];          // 131072
    const int E = in_sizes[27] / 2;     // 8388608

    const int* edge = (const int*)d_in[27];
    const int4* src4 = (const int4*)edge;
    const int* dst = edge + E;

    static bool attr_done = false;
    if (!attr_done) {
        cudaFuncSetAttribute(fused_kernel,
                             cudaFuncAttributeMaxDynamicSharedMemorySize,
                             NMAX);
        attr_done = true;
    }

    NeuronParams p{
        (const float*)d_in[0],  (const float*)d_in[1],
        (const float*)d_in[2],  (const float*)d_in[3],
        (const float*)d_in[4],  (const float*)d_in[5],
        (const float*)d_in[6],  (const float*)d_in[7],
        (const float*)d_in[8],  (const float*)d_in[9],
        (const float*)d_in[10], (const float*)d_in[11],
        (const float*)d_in[12], (const float*)d_in[13],
        (const float*)d_in[14], (const float*)d_in[15],
        (const float*)d_in[16], (const float*)d_in[17],
        (const float*)d_in[18], (const float*)d_in[19],
        (const float*)d_in[20], (const float*)d_in[21],
        (const float*)d_in[22], (const float*)d_in[23],
        (const float*)d_in[24], (const float*)d_in[28],
        (float*)d_out, n};

    fused_kernel<<<NBLK, NTHR, NMAX>>>((const uint4*)d_in[25],
                                       (const uint4*)d_in[26],
                                       src4, dst, E / 4, p);
}

// round 13
// speedup vs baseline: 1.0943x; 1.0943x over previous
#include <cuda_runtime.h>
#include <cuda_bf16.h>

// FlyVisAdExODE: event-driven COBA scatter + AdEx Euler step.
// N = 131072 neurons, E = N*64 = 8388608 edges.
//
// R8: revert R7's full-grid-barrier fusion (regressed 20.6 -> 47.2us).
// Two kernels:
//  K1 scatter: first 128 blocks inline-build the byte activity code table
//     (0 idle / 1 exc / 2 inh) and release via threadfence+atomicAdd; all
//     blocks acquire-poll the flag (one-way sync, ~1us, replaces a 4.3us
//     launch floor), stage the 128KB table to smem, then scatter with packed
//     u32 counter atomics (exc low16 / inh hi16) — deterministic.
//  K2 update: AdEx Euler, 2 neurons/thread (float2), rezeroes g_cnt and
//     g_done for the next launch (zero-at-entry invariant: static init on
//     first call, re-established every call => graph-replay safe).

#define NMAX   131072
#define NBLK   148
#define NTHR   1024
#define NBUILD 128          // builder blocks (NBUILD * NTHR == NMAX)

__device__ unsigned int  g_cnt[NMAX];   // zero-initialized at module load
__device__ unsigned char g_code[NMAX];
__device__ unsigned int  g_done;        // build-complete counter (0 at entry)

__device__ __forceinline__ unsigned ld_acquire(const unsigned* p) {
    unsigned v;
    asm volatile("ld.global.acquire.gpu.u32 %0, [%1];"
                 : "=r"(v) : "l"(p) : "memory");
    return v;
}

__device__ __forceinline__ void emit4(const int* __restrict__ dst, int t,
                                      unsigned c0, unsigned c1,
                                      unsigned c2, unsigned c3) {
    int4 d = __ldg(reinterpret_cast<const int4*>(dst) + t);
    if (c0) atomicAdd(&g_cnt[d.x], (c0 & 1u) | ((c0 & 2u) << 15));
    if (c1) atomicAdd(&g_cnt[d.y], (c1 & 1u) | ((c1 & 2u) << 15));
    if (c2) atomicAdd(&g_cnt[d.z], (c2 & 1u) | ((c2 & 2u) << 15));
    if (c3) atomicAdd(&g_cnt[d.w], (c3 & 1u) | ((c3 & 2u) << 15));
}

__global__ __launch_bounds__(NTHR, 1)
void scatter_kernel(const unsigned* __restrict__ spiked,
                    const unsigned* __restrict__ is_exc,
                    const int4* __restrict__ src4,
                    const int*  __restrict__ dst,
                    int e4) {
    extern __shared__ unsigned char tbl[];          // 131072 bytes

    // ---- inline prep: builder blocks write their 1024-byte code slice ----
    if (blockIdx.x < NBUILD) {
        int i = blockIdx.x * NTHR + threadIdx.x;
        unsigned s = spiked[i];
        unsigned e = is_exc[i];
        g_code[i] = s ? (e ? (unsigned char)1 : (unsigned char)2)
                      : (unsigned char)0;
        __syncthreads();
        if (threadIdx.x == 0) {
            __threadfence();                        // publish g_code slice
            atomicAdd(&g_done, 1u);                 // release
        }
    }

    // ---- one-way wait: all blocks poll until all slices published ----
    if (threadIdx.x == 0) {
        while (ld_acquire(&g_done) < (unsigned)NBUILD) { }
    }
    __syncthreads();

    // ---- stage byte table from L2 into smem (L2-direct loads) ----
    {
        const uint4* gc = reinterpret_cast<const uint4*>(g_code);
        uint4* st = reinterpret_cast<uint4*>(tbl);
        #pragma unroll
        for (int j = 0; j < 8; j++)
            st[threadIdx.x + j * NTHR] = __ldcg(gc + threadIdx.x + j * NTHR);
    }
    __syncthreads();

    // ---- scatter: 8 edges/iter, single combined idle test ----
    const int T = NBLK * NTHR;
    int t = blockIdx.x * NTHR + threadIdx.x;

    for (; t + T < e4; t += 2 * T) {
        int4 s0 = src4[t];
        int4 s1 = src4[t + T];
        unsigned a0 = tbl[s0.x], a1 = tbl[s0.y], a2 = tbl[s0.z], a3 = tbl[s0.w];
        unsigned b0 = tbl[s1.x], b1 = tbl[s1.y], b2 = tbl[s1.z], b3 = tbl[s1.w];
        if ((a0 | a1 | a2 | a3 | b0 | b1 | b2 | b3) != 0u) {
            if (a0 | a1 | a2 | a3) emit4(dst, t,     a0, a1, a2, a3);
            if (b0 | b1 | b2 | b3) emit4(dst, t + T, b0, b1, b2, b3);
        }
    }
    for (; t < e4; t += T) {
        int4 s = src4[t];
        unsigned c0 = tbl[s.x], c1 = tbl[s.y], c2 = tbl[s.z], c3 = tbl[s.w];
        if (c0 | c1 | c2 | c3) emit4(dst, t, c0, c1, c2, c3);
    }
}

// ---------------------------------------------------------------------------
// K2: AdEx Euler update, 2 neurons/thread. Rezeroes g_cnt and g_done.
// ---------------------------------------------------------------------------
struct NeuronParams {
    const float *v, *w, *ge, *gi, *stim, *refr;
    const float *g_L, *delta_T, *v_thresh, *v_rest, *C, *a, *b;
    const float *tau_w, *tau_ge, *tau_gi;
    const float *E_ge, *E_gi, *I_bias, *stim_scale, *Q_ge, *Q_gi;
    const float *v_cut, *v_reset, *t_refrac;
    const float *dt_ptr;
    float* out;
    int n;
};

__device__ __forceinline__ float2 ld2(const float* p, int t) {
    return reinterpret_cast<const float2*>(p)[t];
}

__global__ void update_kernel(NeuronParams p) {
    int t = blockIdx.x * blockDim.x + threadIdx.x;   // N/2 threads
    if (t == 0) g_done = 0u;                         // re-arm flag
    if (t * 2 >= p.n) return;

    const float dt = __ldg(p.dt_ptr);

    uint2 cnt = reinterpret_cast<const uint2*>(g_cnt)[t];
    reinterpret_cast<uint2*>(g_cnt)[t] = make_uint2(0u, 0u);  // re-arm counters

    float2 geL = ld2(p.ge, t),  giL = ld2(p.gi, t);
    float2 Qge = ld2(p.Q_ge, t), Qgi = ld2(p.Q_gi, t);
    float2 vL  = ld2(p.v, t),   wL  = ld2(p.w, t);
    float2 gLv = ld2(p.g_L, t), dTv = ld2(p.delta_T, t);
    float2 vth = ld2(p.v_thresh, t), vrs = ld2(p.v_rest, t);
    float2 Cv  = ld2(p.C, t),   av  = ld2(p.a, t),  bv = ld2(p.b, t);
    float2 twv = ld2(p.tau_w, t), tge = ld2(p.tau_ge, t), tgi = ld2(p.tau_gi, t);
    float2 Ege = ld2(p.E_ge, t), Egi = ld2(p.E_gi, t);
    float2 Ib  = ld2(p.I_bias, t), ss = ld2(p.stim_scale, t);
    float2 st  = ld2(p.stim, t), rf0 = ld2(p.refr, t);
    float2 vc  = ld2(p.v_cut, t), vre = ld2(p.v_reset, t), tre = ld2(p.t_refrac, t);

    float2 vn2, wn2, ge2, gi2, rf2, sp2;

    #pragma unroll
    for (int k = 0; k < 2; k++) {
        unsigned c = k ? cnt.y : cnt.x;
        float ge = (k ? geL.y : geL.x) + (k ? Qge.y : Qge.x) * (float)(c & 0xFFFFu);
        float gi = (k ? giL.y : giL.x) + (k ? Qgi.y : Qgi.x) * (float)(c >> 16);
        float v  = k ? vL.y : vL.x;
        float w  = k ? wL.y : wL.x;
        float gL = k ? gLv.y : gLv.x;
        float dT = k ? dTv.y : dTv.x;
        float vr = k ? vrs.y : vrs.x;

        float I  = (k ? Ib.y : Ib.x) + (k ? ss.y : ss.x) * (k ? st.y : st.x)
                 + ge * ((k ? Ege.y : Ege.x) - v) + gi * ((k ? Egi.y : Egi.x) - v);
        float ex = gL * dT * expf(fminf((v - (k ? vth.y : vth.x)) / dT, 20.0f));
        float dv = (-gL * (v - vr) + ex - w + I) / (k ? Cv.y : Cv.x);
        float dw = (-w + (k ? av.y : av.x) * (v - vr)) / (k ? twv.y : twv.x);

        float refr = k ? rf0.y : rf0.x;
        float vn = (refr <= 0.0f) ? (v + dv * dt) : v;
        float wn = w + dw * dt;
        ge = ge - (ge / (k ? tge.y : tge.x)) * dt;
        gi = gi - (gi / (k ? tgi.y : tgi.x)) * dt;

        bool spk = vn > (k ? vc.y : vc.x);
        vn = spk ? (k ? vre.y : vre.x) : vn;
        wn = spk ? (wn + (k ? bv.y : bv.x)) : wn;
        float rf = (spk ? (k ? tre.y : tre.x) : refr) - dt;

        if (k) { vn2.y = vn; wn2.y = wn; ge2.y = ge; gi2.y = gi; rf2.y = rf; sp2.y = spk ? 1.0f : 0.0f; }
        else   { vn2.x = vn; wn2.x = wn; ge2.x = ge; gi2.x = gi; rf2.x = rf; sp2.x = spk ? 1.0f : 0.0f; }
    }

    const int n2 = p.n / 2;
    float2* out2 = reinterpret_cast<float2*>(p.out);
    out2[t]          = vn2;
    out2[n2 + t]     = wn2;
    out2[2 * n2 + t] = ge2;
    out2[3 * n2 + t] = gi2;
    out2[4 * n2 + t] = rf2;
    out2[5 * n2 + t] = sp2;
}

extern "C" void kernel_launch(void* const* d_in, const int* in_sizes, int n_in,
                              void* d_out, int out_size) {
    const int n = in_sizes[0];          // 131072
    const int E = in_sizes[27] / 2;     // 8388608

    const int* edge = (const int*)d_in[27];
    const int4* src4 = (const int4*)edge;
    const int* dst = edge + E;

    static bool attr_done = false;
    if (!attr_done) {
        cudaFuncSetAttribute(scatter_kernel,
                             cudaFuncAttributeMaxDynamicSharedMemorySize,
                             NMAX);
        attr_done = true;
    }

    // K1: scatter with inline code-build (one-way flag sync)
    scatter_kernel<<<NBLK, NTHR, NMAX>>>((const unsigned*)d_in[25],
                                         (const unsigned*)d_in[26],
                                         src4, dst, E / 4);

    // K2: neuron update (2 neurons/thread), rezeroes g_cnt / g_done
    update_kernel<<<(n / 2 + 255) / 256, 256>>>(
        NeuronParams{
            (const float*)d_in[0],  (const float*)d_in[1],
            (const float*)d_in[2],  (const float*)d_in[3],
            (const float*)d_in[4],  (const float*)d_in[5],
            (const float*)d_in[6],  (const float*)d_in[7],
            (const float*)d_in[8],  (const float*)d_in[9],
            (const float*)d_in[10], (const float*)d_in[11],
            (const float*)d_in[12], (const float*)d_in[13],
            (const float*)d_in[14], (const float*)d_in[15],
            (const float*)d_in[16], (const float*)d_in[17],
            (const float*)d_in[18], (const float*)d_in[19],
            (const float*)d_in[20], (const float*)d_in[21],
            (const float*)d_in[22], (const float*)d_in[23],
            (const float*)d_in[24], (const float*)d_in[28],
            (float*)d_out, n});
}

// round 14
// speedup vs baseline: 2.2747x; 2.0787x over previous
#include <cuda_runtime.h>
#include <cuda_bf16.h>

// FlyVisAdExODE: event-driven COBA scatter + AdEx Euler step.
// N = 131072 neurons, E = N*64 = 8388608 edges.
//
// R9: back to the proven 3-kernel split (R6, 20.58us). Single change:
// NIBBLE-packed activity codes (2 codes/byte, 64KB table) so TWO 1024-thread
// blocks fit per SM (64 warps, 2x occupancy) to hide LDS/L2 latency in the
// scatter. __launch_bounds__(1024,2) caps regs at 32. Update kernel back to
// scalar 1-neuron/thread (float2 variant measured 9.3us — occupancy loss).
// Packed u32 counter atomics (exc low16 / inh hi16) stay deterministic.
// g_cnt zero-at-entry invariant: static zero-init on first call, re-armed by
// update_kernel every call => graph-replay safe.

#define NMAX 131072
#define TBLB (NMAX / 2)     // 65536 bytes of nibble codes

__device__ unsigned int  g_cnt[NMAX];   // zero-initialized at module load
__device__ unsigned char g_code[TBLB];  // nibble codes: 0 idle, 1 exc, 2 inh

// ---------------------------------------------------------------------------
// Phase 1: build nibble codes, 4 neurons/thread -> uchar2 store.
// spiked / is_excitatory are 4-byte (int32 or float32): nonzero-u32 test is
// correct for both encodings.
// ---------------------------------------------------------------------------
__global__ void prep_kernel(const uint4* __restrict__ spiked,
                            const uint4* __restrict__ is_exc) {
    int t = blockIdx.x * blockDim.x + threadIdx.x;   // N/4 threads
    uint4 s = spiked[t];
    uint4 e = is_exc[t];
    unsigned c0 = s.x ? (e.x ? 1u : 2u) : 0u;
    unsigned c1 = s.y ? (e.y ? 1u : 2u) : 0u;
    unsigned c2 = s.z ? (e.z ? 1u : 2u) : 0u;
    unsigned c3 = s.w ? (e.w ? 1u : 2u) : 0u;
    uchar2 o;
    o.x = (unsigned char)(c0 | (c1 << 4));
    o.y = (unsigned char)(c2 | (c3 << 4));
    reinterpret_cast<uchar2*>(g_code)[t] = o;
}

// ---------------------------------------------------------------------------
// Phase 2: scatter. 64KB nibble table in smem, 2 blocks/SM, 8 edges/iter
// with single combined idle test; predicated int4 dst loads; packed atomics.
// ---------------------------------------------------------------------------
__device__ __forceinline__ unsigned gather(const unsigned char* tbl, int s) {
    return (tbl[s >> 1] >> ((s & 1) << 2)) & 0xFu;
}

__device__ __forceinline__ void emit4(const int* __restrict__ dst, int t,
                                      unsigned c0, unsigned c1,
                                      unsigned c2, unsigned c3) {
    int4 d = __ldg(reinterpret_cast<const int4*>(dst) + t);
    if (c0) atomicAdd(&g_cnt[d.x], (c0 & 1u) | ((c0 & 2u) << 15));
    if (c1) atomicAdd(&g_cnt[d.y], (c1 & 1u) | ((c1 & 2u) << 15));
    if (c2) atomicAdd(&g_cnt[d.z], (c2 & 1u) | ((c2 & 2u) << 15));
    if (c3) atomicAdd(&g_cnt[d.w], (c3 & 1u) | ((c3 & 2u) << 15));
}

#define SBLK 296            // 2 blocks per SM

__global__ __launch_bounds__(1024, 2)
void scatter_kernel(const int4* __restrict__ src4,
                    const int*  __restrict__ dst,
                    int e4) {
    extern __shared__ unsigned char tbl[];          // 65536 bytes

    // stage nibble table from L2 into smem (4 uint4 per thread)
    {
        const uint4* gc = reinterpret_cast<const uint4*>(g_code);
        uint4* st = reinterpret_cast<uint4*>(tbl);
        #pragma unroll
        for (int j = 0; j < 4; j++)
            st[threadIdx.x + j * 1024] = __ldcg(gc + threadIdx.x + j * 1024);
    }
    __syncthreads();

    const int T = SBLK * 1024;
    int t = blockIdx.x * 1024 + threadIdx.x;

    for (; t + T < e4; t += 2 * T) {
        int4 s0 = src4[t];
        int4 s1 = src4[t + T];
        unsigned a0 = gather(tbl, s0.x), a1 = gather(tbl, s0.y);
        unsigned a2 = gather(tbl, s0.z), a3 = gather(tbl, s0.w);
        unsigned b0 = gather(tbl, s1.x), b1 = gather(tbl, s1.y);
        unsigned b2 = gather(tbl, s1.z), b3 = gather(tbl, s1.w);
        if ((a0 | a1 | a2 | a3 | b0 | b1 | b2 | b3) != 0u) {
            if (a0 | a1 | a2 | a3) emit4(dst, t,     a0, a1, a2, a3);
            if (b0 | b1 | b2 | b3) emit4(dst, t + T, b0, b1, b2, b3);
        }
    }
    for (; t < e4; t += T) {
        int4 s = src4[t];
        unsigned c0 = gather(tbl, s.x), c1 = gather(tbl, s.y);
        unsigned c2 = gather(tbl, s.z), c3 = gather(tbl, s.w);
        if (c0 | c1 | c2 | c3) emit4(dst, t, c0, c1, c2, c3);
    }
}

// ---------------------------------------------------------------------------
// Phase 3: AdEx Euler update (scalar, 1 neuron/thread). Rezeroes g_cnt.
// ---------------------------------------------------------------------------
struct NeuronParams {
    const float *v, *w, *ge, *gi, *stim, *refr;
    const float *g_L, *delta_T, *v_thresh, *v_rest, *C, *a, *b;
    const float *tau_w, *tau_ge, *tau_gi;
    const float *E_ge, *E_gi, *I_bias, *stim_scale, *Q_ge, *Q_gi;
    const float *v_cut, *v_reset, *t_refrac;
    const float *dt_ptr;
    float* out;
    int n;
};

__global__ void update_kernel(NeuronParams p) {
    int i = blockIdx.x * blockDim.x + threadIdx.x;
    if (i >= p.n) return;

    const float dt = __ldg(p.dt_ptr);

    unsigned int cnt = g_cnt[i];
    g_cnt[i] = 0u;                       // re-arm for next launch
    float ge = p.ge[i] + p.Q_ge[i] * (float)(cnt & 0xFFFFu);
    float gi = p.gi[i] + p.Q_gi[i] * (float)(cnt >> 16);

    float v  = p.v[i];
    float w  = p.w[i];
    float gL = p.g_L[i];
    float dT = p.delta_T[i];
    float vr = p.v_rest[i];

    float I  = p.I_bias[i] + p.stim_scale[i] * p.stim[i]
             + ge * (p.E_ge[i] - v) + gi * (p.E_gi[i] - v);
    float ex = gL * dT * expf(fminf((v - p.v_thresh[i]) / dT, 20.0f));
    float dv = (-gL * (v - vr) + ex - w + I) / p.C[i];
    float dw = (-w + p.a[i] * (v - vr)) / p.tau_w[i];

    float refr = p.refr[i];
    float vn = (refr <= 0.0f) ? (v + dv * dt) : v;
    float wn = w + dw * dt;
    ge = ge - (ge / p.tau_ge[i]) * dt;
    gi = gi - (gi / p.tau_gi[i]) * dt;

    bool spk = vn > p.v_cut[i];
    vn = spk ? p.v_reset[i] : vn;
    wn = spk ? (wn + p.b[i]) : wn;
    float rf = (spk ? p.t_refrac[i] : refr) - dt;

    const int n = p.n;
    float* out = p.out;
    out[i]         = vn;
    out[n + i]     = wn;
    out[2 * n + i] = ge;
    out[3 * n + i] = gi;
    out[4 * n + i] = rf;
    out[5 * n + i] = spk ? 1.0f : 0.0f;
}

extern "C" void kernel_launch(void* const* d_in, const int* in_sizes, int n_in,
                              void* d_out, int out_size) {
    const int n = in_sizes[0];          // 131072
    const int E = in_sizes[27] / 2;     // 8388608

    const int* edge = (const int*)d_in[27];
    const int4* src4 = (const int4*)edge;
    const int* dst = edge + E;

    static bool attr_done = false;
    if (!attr_done) {
        cudaFuncSetAttribute(scatter_kernel,
                             cudaFuncAttributeMaxDynamicSharedMemorySize,
                             TBLB);
        attr_done = true;
    }

    // Phase 1: nibble code build, 4 neurons/thread
    prep_kernel<<<n / 4 / 256, 256>>>((const uint4*)d_in[25],
                                      (const uint4*)d_in[26]);

    // Phase 2: scatter, 296 blocks (2/SM) x 1024 threads, 64KB smem each
    scatter_kernel<<<SBLK, 1024, TBLB>>>(src4, dst, E / 4);

    // Phase 3: neuron update (also rezeroes g_cnt)
    update_kernel<<<(n + 255) / 256, 256>>>(
        NeuronParams{
            (const float*)d_in[0],  (const float*)d_in[1],
            (const float*)d_in[2],  (const float*)d_in[3],
            (const float*)d_in[4],  (const float*)d_in[5],
            (const float*)d_in[6],  (const float*)d_in[7],
            (const float*)d_in[8],  (const float*)d_in[9],
            (const float*)d_in[10], (const float*)d_in[11],
            (const float*)d_in[12], (const float*)d_in[13],
            (const float*)d_in[14], (const float*)d_in[15],
            (const float*)d_in[16], (const float*)d_in[17],
            (const float*)d_in[18], (const float*)d_in[19],
            (const float*)d_in[20], (const float*)d_in[21],
            (const float*)d_in[22], (const float*)d_in[23],
            (const float*)d_in[24], (const float*)d_in[28],
            (float*)d_out, n});
}